// round 4
// baseline (speedup 1.0000x reference)
#include <cuda_runtime.h>
#include <cstdint>
#include <math.h>

#define BB 16
#define TT 4096
#define JJ 17
#define CC 128
#define HH 512
#define KK 2048
#define BT (BB*TT)

#define SEL_ELEMS (BB*KK*JJ*CC)   // 71303168
#define IDX_ELEMS (BB*KK)         // 32768

// ---- scratch (static device arrays; no allocation allowed) ----
__device__ float g_stn[BT*CC];          // layernormed joint-mean  [B*T, C]
__device__ float g_gc_part[BB*32*CC];   // partial sums for global context
__device__ float g_gc[BB*CC];           // global context  [B, C]
__device__ float g_scores[BT];          // raw MLP scores  [B*T]
__device__ int   g_selidx[BB*KK];       // selected indices, ascending per batch
__device__ float g_gate[BB*KK];         // 1 + 0.1*sigmoid(score)

// ---------------- f32x2 helpers (Blackwell packed fp32) ----------------
__device__ __forceinline__ unsigned long long pack2(float x) {
    unsigned long long r;
    asm("mov.b64 %0, {%1, %1};" : "=l"(r) : "f"(x));
    return r;
}
__device__ __forceinline__ unsigned long long fma2(unsigned long long a,
                                                   unsigned long long b,
                                                   unsigned long long c) {
    unsigned long long d;
    asm("fma.rn.f32x2 %0, %1, %2, %3;" : "=l"(d) : "l"(a), "l"(b), "l"(c));
    return d;
}
__device__ __forceinline__ float2 unpack2(unsigned long long v) {
    float lo, hi;
    asm("mov.b64 {%0, %1}, %2;" : "=f"(lo), "=f"(hi) : "l"(v));
    return make_float2(lo, hi);
}

__device__ __forceinline__ float gelu_exact(float x) {
    return 0.5f * x * (1.0f + erff(x * 0.70710678118654752440f));
}

// ---------------- Kernel 1: joint mean + LayerNorm ----------------
__global__ void __launch_bounds__(128) mean_ln_kernel(
    const float* __restrict__ tokens,
    const float* __restrict__ ln_w,
    const float* __restrict__ ln_b)
{
    int bt = blockIdx.x;
    int c  = threadIdx.x;
    const float* src = tokens + (size_t)bt * (JJ*CC) + c;
    float s = 0.f;
#pragma unroll
    for (int j = 0; j < JJ; ++j) s += src[(size_t)j*CC];
    float st = s * (1.0f/17.0f);

    __shared__ float red[64];
    float v = st, v2 = st*st;
#pragma unroll
    for (int o = 16; o; o >>= 1) {
        v  += __shfl_down_sync(0xffffffffu, v,  o);
        v2 += __shfl_down_sync(0xffffffffu, v2, o);
    }
    int wid = c >> 5, lane = c & 31;
    if (lane == 0) { red[wid] = v; red[32+wid] = v2; }
    __syncthreads();
    if (c == 0) {
        float a = red[0]+red[1]+red[2]+red[3];
        float b = red[32]+red[33]+red[34]+red[35];
        red[40] = a * (1.0f/128.0f);
        red[41] = b * (1.0f/128.0f);
    }
    __syncthreads();
    float mu  = red[40];
    float var = red[41] - mu*mu;
    float inv = rsqrtf(var + 1e-5f);
    g_stn[(size_t)bt*CC + c] = (st - mu) * inv * ln_w[c] + ln_b[c];
}

// ---------------- Kernel 2/3: global context reduce ----------------
__global__ void __launch_bounds__(128) gc_partial_kernel()
{
    int b = blockIdx.x, chunk = blockIdx.y, c = threadIdx.x;
    const float* p = g_stn + ((size_t)(b*TT + chunk*128))*CC + c;
    float s = 0.f;
#pragma unroll 8
    for (int t = 0; t < 128; ++t) s += p[(size_t)t*CC];
    g_gc_part[(b*32 + chunk)*CC + c] = s;
}

__global__ void __launch_bounds__(128) gc_final_kernel()
{
    int b = blockIdx.x, c = threadIdx.x;
    float s = 0.f;
#pragma unroll
    for (int k = 0; k < 32; ++k) s += g_gc_part[(b*32 + k)*CC + c];
    g_gc[b*CC + c] = s * (1.0f/4096.0f);
}

// ---------------- Kernel 4: MLP scoring (fp32 GEMM via f32x2) ----------------
// 512 threads; block tile 128 tokens x 256 h per chunk (2 chunks of H=512).
// Thread tile: 4 tokens x 16 h  (acc = 32 u64 regs -> 4 warps/SMSP).
//   x: natural [t][k] layout, pitch 132 (broadcast LDS.32, conflict-free)
//   w: [k][256], thread's 16 h = tx*4 + {0..3} + 64*q (consecutive-16B LDS.128)
#define XPITCH 132
#define PPITCH 132
#define MLP_SMEM ((128*XPITCH + 128*256 + 16*PPITCH) * 4)
__global__ void __launch_bounds__(512, 1) mlp_kernel(
    const float* __restrict__ W1,
    const float* __restrict__ b1,
    const float* __restrict__ W2,
    const float* __restrict__ b2)
{
    extern __shared__ float sh[];
    float* xs   = sh;                        // [128 t][pitch 132]
    float* ws   = sh + 128*XPITCH;           // [128 k][256 h]
    float* part = sh + 128*XPITCH + 128*256; // [16][pitch 132]

    int tid = threadIdx.x;
    int g0  = blockIdx.x * 128;
    int b   = g0 >> 12;

    // stage x (natural layout, +gc); fully coalesced, conflict-free stores
#pragma unroll
    for (int r = 0; r < 8; ++r) {
        int i  = r*512 + tid;
        int t  = i >> 5;
        int kq = (i & 31) * 4;
        float4 x4 = *(const float4*)(g_stn + (size_t)(g0 + t)*CC + kq);
        float4 g4 = *(const float4*)(g_gc + b*CC + kq);
        x4.x += g4.x; x4.y += g4.y; x4.z += g4.z; x4.w += g4.w;
        *(float4*)(xs + t*XPITCH + kq) = x4;
    }

    int tx = tid & 15;            // h-quad group: h = tx*4+{0..3} + 64*q
    int ty = tid >> 4;            // token group:  t = ty*4+{0..3}  (32 groups)
    int t0 = ty * 4;

    float sp[4] = {0.f, 0.f, 0.f, 0.f};

    for (int hc = 0; hc < 2; ++hc) {
        __syncthreads();   // xs ready / previous ws consumed
#pragma unroll
        for (int r = 0; r < 16; ++r) {
            int i = r*512 + tid;
            int k = i >> 6;
            int q = (i & 63) * 4;
            *(float4*)(ws + k*256 + q) =
                *(const float4*)(W1 + (size_t)k*HH + hc*256 + q);
        }
        __syncthreads();

        unsigned long long acc[4][8];
#pragma unroll
        for (int i = 0; i < 4; ++i)
#pragma unroll
            for (int j = 0; j < 8; ++j) acc[i][j] = 0ull;

#pragma unroll 2
        for (int k = 0; k < 128; ++k) {
            // x: 4 tokens, broadcast scalar loads
            const float* xc = xs + k;
            unsigned long long xp[4];
#pragma unroll
            for (int i = 0; i < 4; ++i)
                xp[i] = pack2(xc[(t0+i)*XPITCH]);
            // w: 16 h as 4 conflict-free LDS.128 (h-pairs packed free)
            const float* wr = ws + k*256 + tx*4;
            ulonglong2 w0 = *(const ulonglong2*)(wr);
            ulonglong2 w1 = *(const ulonglong2*)(wr + 64);
            ulonglong2 w2 = *(const ulonglong2*)(wr + 128);
            ulonglong2 w3 = *(const ulonglong2*)(wr + 192);
#pragma unroll
            for (int i = 0; i < 4; ++i) {
                acc[i][0] = fma2(xp[i], w0.x, acc[i][0]);
                acc[i][1] = fma2(xp[i], w0.y, acc[i][1]);
                acc[i][2] = fma2(xp[i], w1.x, acc[i][2]);
                acc[i][3] = fma2(xp[i], w1.y, acc[i][3]);
                acc[i][4] = fma2(xp[i], w2.x, acc[i][4]);
                acc[i][5] = fma2(xp[i], w2.y, acc[i][5]);
                acc[i][6] = fma2(xp[i], w3.x, acc[i][6]);
                acc[i][7] = fma2(xp[i], w3.y, acc[i][7]);
            }
        }

        // epilogue: gelu + dot with W2 for this chunk
#pragma unroll
        for (int q = 0; q < 4; ++q) {
            int hb = hc*256 + q*64 + tx*4;
            float4 b1q = *(const float4*)(b1 + hb);
            float4 w2q = *(const float4*)(W2 + hb);
#pragma unroll
            for (int i = 0; i < 4; ++i) {
                float2 e0 = unpack2(acc[i][q*2]);
                float2 e1 = unpack2(acc[i][q*2+1]);
                sp[i] += gelu_exact(e0.x + b1q.x) * w2q.x;
                sp[i] += gelu_exact(e0.y + b1q.y) * w2q.y;
                sp[i] += gelu_exact(e1.x + b1q.z) * w2q.z;
                sp[i] += gelu_exact(e1.y + b1q.w) * w2q.w;
            }
        }
    }

    __syncthreads();
#pragma unroll
    for (int i = 0; i < 4; ++i)
        part[tx*PPITCH + t0 + i] = sp[i];
    __syncthreads();
    if (tid < 128) {
        float s = b2[0];
#pragma unroll
        for (int x = 0; x < 16; ++x) s += part[x*PPITCH + tid];
        g_scores[g0 + tid] = s;
    }
}

// ---------------- Kernel 5: normalize + top-k + compact ----------------
__device__ __forceinline__ unsigned long long mk_key(float f, int i) {
    unsigned u = __float_as_uint(f);
    u = (u & 0x80000000u) ? ~u : (u | 0x80000000u);  // order-preserving
    return (((unsigned long long)(~u)) << 32) | (unsigned)i; // desc score, asc idx
}

#define TOPK_SMEM (16384 + 32768 + 16384 + 512)
__global__ void __launch_bounds__(1024) topk_kernel(
    float* __restrict__ out_idx, float* __restrict__ out_scores)
{
    extern __shared__ unsigned char shraw[];
    float*              sc   = (float*)shraw;                         // [4096]
    unsigned long long* key  = (unsigned long long*)(shraw + 16384);  // [4096]
    int*                flag = (int*)(shraw + 16384 + 32768);         // [4096]
    float*              redf = (float*)(shraw + 16384 + 32768 + 16384); // 64 f
    int*                redi = (int*)(redf + 64);                     // 64 i

    int b = blockIdx.x, tid = threadIdx.x;
    int lane = tid & 31, wid = tid >> 5;
    int base4 = tid * 4;

    float4 v = *(const float4*)(g_scores + b*TT + base4);
    float s = v.x + v.y + v.z + v.w;
#pragma unroll
    for (int o = 16; o; o >>= 1) s += __shfl_down_sync(0xffffffffu, s, o);
    if (lane == 0) redf[wid] = s;
    __syncthreads();
    if (tid == 0) {
        float a = 0.f;
        for (int i = 0; i < 32; ++i) a += redf[i];
        redf[32] = a * (1.0f/TT);
    }
    __syncthreads();
    float mean = redf[32];
    float d0 = v.x-mean, d1 = v.y-mean, d2 = v.z-mean, d3 = v.w-mean;
    float q = d0*d0 + d1*d1 + d2*d2 + d3*d3;
    __syncthreads();
#pragma unroll
    for (int o = 16; o; o >>= 1) q += __shfl_down_sync(0xffffffffu, q, o);
    if (lane == 0) redf[wid] = q;
    __syncthreads();
    if (tid == 0) {
        float a = 0.f;
        for (int i = 0; i < 32; ++i) a += redf[i];
        redf[33] = 1.0f / (sqrtf(a * (1.0f/TT)) + 1e-6f);
    }
    __syncthreads();
    float inv = redf[33];
    float n0 = d0*inv, n1 = d1*inv, n2 = d2*inv, n3 = d3*inv;

    sc[base4+0] = n0; sc[base4+1] = n1; sc[base4+2] = n2; sc[base4+3] = n3;
    *(float4*)(out_scores + b*TT + base4) = make_float4(n0, n1, n2, n3);
    key[base4+0] = mk_key(n0, base4+0);
    key[base4+1] = mk_key(n1, base4+1);
    key[base4+2] = mk_key(n2, base4+2);
    key[base4+3] = mk_key(n3, base4+3);
    flag[base4+0] = 0; flag[base4+1] = 0; flag[base4+2] = 0; flag[base4+3] = 0;
    __syncthreads();

    // bitonic sort 4096 keys ascending
    for (int kk = 2; kk <= 4096; kk <<= 1) {
        for (int j = kk >> 1; j > 0; j >>= 1) {
#pragma unroll
            for (int p = 0; p < 4; ++p) {
                int i = tid + p*1024;
                int ixj = i ^ j;
                if (ixj > i) {
                    unsigned long long a = key[i], c2 = key[ixj];
                    bool asc = ((i & kk) == 0);
                    if ((a > c2) == asc) { key[i] = c2; key[ixj] = a; }
                }
            }
            __syncthreads();
        }
    }

    // mark top K (positions 0..2047)
    {
        int idx = (int)(unsigned)(key[tid] & 0xffffffffull);
        flag[idx] = 1;
        idx = (int)(unsigned)(key[tid + 1024] & 0xffffffffull);
        flag[idx] = 1;
    }
    __syncthreads();

    // prefix scan of flags, compact ascending
    int f0 = flag[base4], f1 = flag[base4+1], f2 = flag[base4+2], f3 = flag[base4+3];
    int tot = f0 + f1 + f2 + f3;
    int x = tot;
#pragma unroll
    for (int o = 1; o < 32; o <<= 1) {
        int y = __shfl_up_sync(0xffffffffu, x, o);
        if (lane >= o) x += y;
    }
    if (lane == 31) redi[wid] = x;
    __syncthreads();
    if (wid == 0) {
        int y = redi[lane];
        int z = y;
#pragma unroll
        for (int o = 1; o < 32; o <<= 1) {
            int w2 = __shfl_up_sync(0xffffffffu, z, o);
            if (lane >= o) z += w2;
        }
        redi[32 + lane] = z - y;   // exclusive
    }
    __syncthreads();
    int off = redi[32 + wid] + (x - tot);

    int flags[4] = {f0, f1, f2, f3};
#pragma unroll
    for (int qq = 0; qq < 4; ++qq) {
        if (flags[qq]) {
            int idx = base4 + qq;
            int pos = b*KK + off;
            g_selidx[pos] = idx;
            out_idx[pos]  = (float)idx;
            g_gate[pos]   = 1.0f + 0.1f * (1.0f / (1.0f + expf(-sc[idx])));
            ++off;
        }
    }
}

// ---------------- Kernel 6: gather + gate ----------------
__global__ void __launch_bounds__(256) gather_kernel(
    const float* __restrict__ tokens, float* __restrict__ out_sel)
{
    int bk  = blockIdx.x;          // b*K + kk
    int b   = bk >> 11;
    int idx = g_selidx[bk];
    float gate = g_gate[bk];
    const float4* src = (const float4*)(tokens + ((size_t)(b*TT + idx)) * (JJ*CC));
    float4* dst = (float4*)(out_sel + (size_t)bk * (JJ*CC));
#pragma unroll 2
    for (int i = threadIdx.x; i < (JJ*CC)/4; i += 256) {
        float4 v = src[i];
        v.x *= gate; v.y *= gate; v.z *= gate; v.w *= gate;
        dst[i] = v;
    }
}

// ---------------- launch ----------------
extern "C" void kernel_launch(void* const* d_in, const int* in_sizes, int n_in,
                              void* d_out, int out_size)
{
    const float* tokens = (const float*)d_in[0];
    const float* ln_w   = (const float*)d_in[1];
    const float* ln_b   = (const float*)d_in[2];
    const float* W1     = (const float*)d_in[3];
    const float* b1     = (const float*)d_in[4];
    const float* W2     = (const float*)d_in[5];
    const float* b2     = (const float*)d_in[6];

    float* out        = (float*)d_out;
    float* out_sel    = out;                       // [B,K,J,C]
    float* out_idx    = out + SEL_ELEMS;           // [B,K]
    float* out_scores = out_idx + IDX_ELEMS;       // [B,T]

    cudaFuncSetAttribute(mlp_kernel,
        cudaFuncAttributeMaxDynamicSharedMemorySize, MLP_SMEM);
    cudaFuncSetAttribute(topk_kernel,
        cudaFuncAttributeMaxDynamicSharedMemorySize, TOPK_SMEM);

    mean_ln_kernel<<<BT, 128>>>(tokens, ln_w, ln_b);
    gc_partial_kernel<<<dim3(BB, 32), 128>>>();
    gc_final_kernel<<<BB, 128>>>();
    mlp_kernel<<<BT/128, 512, MLP_SMEM>>>(W1, b1, W2, b2);
    topk_kernel<<<BB, 1024, TOPK_SMEM>>>(out_idx, out_scores);
    gather_kernel<<<BB*KK, 256>>>(tokens, out_sel);
}

// round 6
// speedup vs baseline: 1.1259x; 1.1259x over previous
#include <cuda_runtime.h>
#include <cuda_bf16.h>
#include <cstdint>
#include <math.h>

#define BB 16
#define TT 4096
#define JJ 17
#define CC 128
#define HH 512
#define KK 2048
#define BT (BB*TT)

#define SEL_ELEMS (BB*KK*JJ*CC)   // 71303168
#define IDX_ELEMS (BB*KK)         // 32768

// ---- scratch (static device arrays; no allocation allowed) ----
__device__ float g_stn[BT*CC];          // layernormed joint-mean  [B*T, C]
__device__ float g_gc_part[BB*32*CC];   // partial sums for global context
__device__ float g_gc[BB*CC];           // global context  [B, C]
__device__ float g_scores[BT];          // raw MLP scores  [B*T]
__device__ int   g_selidx[BB*KK];       // selected indices, ascending per batch
__device__ float g_gate[BB*KK];         // 1 + 0.1*sigmoid(score)
// W1 split into 3 bf16 components, [k][h] layout (k rows, h contiguous)
__device__ __align__(16) __nv_bfloat16 g_Wh[CC*HH];
__device__ __align__(16) __nv_bfloat16 g_Wm[CC*HH];
__device__ __align__(16) __nv_bfloat16 g_Wl[CC*HH];

__device__ __forceinline__ float gelu_exact(float x) {
    return 0.5f * x * (1.0f + erff(x * 0.70710678118654752440f));
}

__device__ __forceinline__ uint32_t smem_u32(const void* p) {
    uint32_t a;
    asm("{ .reg .u64 t; cvta.to.shared.u64 t, %1; cvt.u32.u64 %0, t; }"
        : "=r"(a) : "l"(p));
    return a;
}
__device__ __forceinline__ void ldmatrix_x4(uint32_t* r, uint32_t addr) {
    asm volatile("ldmatrix.sync.aligned.m8n8.x4.shared.b16 {%0,%1,%2,%3}, [%4];"
                 : "=r"(r[0]), "=r"(r[1]), "=r"(r[2]), "=r"(r[3]) : "r"(addr));
}
__device__ __forceinline__ void ldmatrix_x2_t(uint32_t& b0, uint32_t& b1, uint32_t addr) {
    asm volatile("ldmatrix.sync.aligned.m8n8.x2.trans.shared.b16 {%0,%1}, [%2];"
                 : "=r"(b0), "=r"(b1) : "r"(addr));
}
__device__ __forceinline__ void mma16816(float* d, const uint32_t* a,
                                         uint32_t b0, uint32_t b1) {
    asm volatile(
        "mma.sync.aligned.m16n8k16.row.col.f32.bf16.bf16.f32 "
        "{%0,%1,%2,%3}, {%4,%5,%6,%7}, {%8,%9}, {%0,%1,%2,%3};"
        : "+f"(d[0]), "+f"(d[1]), "+f"(d[2]), "+f"(d[3])
        : "r"(a[0]), "r"(a[1]), "r"(a[2]), "r"(a[3]), "r"(b0), "r"(b1));
}
__device__ __forceinline__ void cp_async16(uint32_t dst, const void* src) {
    asm volatile("cp.async.cg.shared.global [%0], [%1], 16;"
                 :: "r"(dst), "l"(src));
}
#define CP_COMMIT() asm volatile("cp.async.commit_group;" ::: "memory")
#define CP_WAIT(N)  asm volatile("cp.async.wait_group %0;" :: "n"(N) : "memory")

// ---------------- Kernel 0: split W1 into bf16 hi/mid/lo, [k][h] ----------------
__global__ void __launch_bounds__(256) split_w_kernel(const float* __restrict__ W1)
{
    int idx = blockIdx.x * 256 + threadIdx.x;   // = k*512 + h, 0..65535
    float w = W1[idx];
    __nv_bfloat16 bh = __float2bfloat16(w);
    float r1 = w - __bfloat162float(bh);
    __nv_bfloat16 bm = __float2bfloat16(r1);
    float r2 = r1 - __bfloat162float(bm);
    __nv_bfloat16 bl = __float2bfloat16(r2);
    g_Wh[idx] = bh; g_Wm[idx] = bm; g_Wl[idx] = bl;
}

// ---------------- Kernel 1: joint mean + LayerNorm ----------------
__global__ void __launch_bounds__(128) mean_ln_kernel(
    const float* __restrict__ tokens,
    const float* __restrict__ ln_w,
    const float* __restrict__ ln_b)
{
    int bt = blockIdx.x;
    int c  = threadIdx.x;
    const float* src = tokens + (size_t)bt * (JJ*CC) + c;
    float s = 0.f;
#pragma unroll
    for (int j = 0; j < JJ; ++j) s += src[(size_t)j*CC];
    float st = s * (1.0f/17.0f);

    __shared__ float red[64];
    float v = st, v2 = st*st;
#pragma unroll
    for (int o = 16; o; o >>= 1) {
        v  += __shfl_down_sync(0xffffffffu, v,  o);
        v2 += __shfl_down_sync(0xffffffffu, v2, o);
    }
    int wid = c >> 5, lane = c & 31;
    if (lane == 0) { red[wid] = v; red[32+wid] = v2; }
    __syncthreads();
    if (c == 0) {
        float a = red[0]+red[1]+red[2]+red[3];
        float b = red[32]+red[33]+red[34]+red[35];
        red[40] = a * (1.0f/128.0f);
        red[41] = b * (1.0f/128.0f);
    }
    __syncthreads();
    float mu  = red[40];
    float var = red[41] - mu*mu;
    float inv = rsqrtf(var + 1e-5f);
    g_stn[(size_t)bt*CC + c] = (st - mu) * inv * ln_w[c] + ln_b[c];
}

// ---------------- Kernel 2/3: global context reduce ----------------
__global__ void __launch_bounds__(128) gc_partial_kernel()
{
    int b = blockIdx.x, chunk = blockIdx.y, c = threadIdx.x;
    const float* p = g_stn + ((size_t)(b*TT + chunk*128))*CC + c;
    float s = 0.f;
#pragma unroll 8
    for (int t = 0; t < 128; ++t) s += p[(size_t)t*CC];
    g_gc_part[(b*32 + chunk)*CC + c] = s;
}

__global__ void __launch_bounds__(128) gc_final_kernel()
{
    int b = blockIdx.x, c = threadIdx.x;
    float s = 0.f;
#pragma unroll
    for (int k = 0; k < 32; ++k) s += g_gc_part[(b*32 + k)*CC + c];
    g_gc[b*CC + c] = s * (1.0f/4096.0f);
}

// ---------------- Kernel 4: MLP scoring via mma.sync bf16 3-split ----------------
// 512 threads/CTA, one 128-token tile; H processed in 8 chunks of 64.
// Warp w: tokens (w&7)*16, n-half (w>>3)*32 of each chunk.
// 6 product passes: XhWh, XmWh, XlWh, XhWm, XmWm, XhWl.
#define XPB 272               // X row pitch bytes  (bank stride 4)
#define WPB 144               // W row pitch bytes  (bank stride 4)
#define OFF_B1   0
#define OFF_W2   2048
#define OFF_PART 4096         // 2*128 floats
#define OFF_X    5120         // 3 * 128*272 = 104448
#define XCOMP    (128*XPB)    // 34816
#define OFF_W    109568       // 2 * 3*128*144 = 110592
#define WBUF     (3*128*WPB)  // 55296
#define WCOMP    (128*WPB)    // 18432
#define MLP_SMEM 220160

__global__ void __launch_bounds__(512, 1) mlp_kernel(
    const float* __restrict__ b1v,
    const float* __restrict__ W2v,
    const float* __restrict__ b2v)
{
    extern __shared__ unsigned char smraw[];
    uint32_t sb = smem_u32(smraw);
    float* s_b1  = (float*)(smraw + OFF_B1);
    float* s_w2  = (float*)(smraw + OFF_W2);
    float* s_prt = (float*)(smraw + OFF_PART);

    int tid = threadIdx.x, w = tid >> 5, lane = tid & 31;
    int g0 = blockIdx.x * 128, b = g0 >> 12;

    if (tid < 512) { s_b1[tid] = b1v[tid]; s_w2[tid] = W2v[tid]; }

    // ---- stage X: 3 bf16 split components, padded rows ----
#pragma unroll
    for (int r = 0; r < 8; ++r) {
        int i  = r*512 + tid;          // 128 t x 32 k-quads
        int t  = i >> 5;
        int kq = (i & 31) * 4;
        float4 x4 = *(const float4*)(g_stn + (size_t)(g0 + t)*CC + kq);
        float4 g4 = *(const float4*)(g_gc + b*CC + kq);
        float xv[4] = {x4.x + g4.x, x4.y + g4.y, x4.z + g4.z, x4.w + g4.w};
        unsigned long long ph = 0, pm = 0, pl = 0;
#pragma unroll
        for (int e = 0; e < 4; ++e) {
            float x = xv[e];
            __nv_bfloat16 bh = __float2bfloat16(x);
            float r1 = x - __bfloat162float(bh);
            __nv_bfloat16 bm = __float2bfloat16(r1);
            float r2 = r1 - __bfloat162float(bm);
            __nv_bfloat16 bl = __float2bfloat16(r2);
            ph |= (unsigned long long)__bfloat16_as_ushort(bh) << (16*e);
            pm |= (unsigned long long)__bfloat16_as_ushort(bm) << (16*e);
            pl |= (unsigned long long)__bfloat16_as_ushort(bl) << (16*e);
        }
        int off = t*XPB + kq*2;
        *(unsigned long long*)(smraw + OFF_X + 0*XCOMP + off) = ph;
        *(unsigned long long*)(smraw + OFF_X + 1*XCOMP + off) = pm;
        *(unsigned long long*)(smraw + OFF_X + 2*XCOMP + off) = pl;
    }

    // ---- W chunk stage (cp.async, [k][64h] per comp, padded rows) ----
    const __nv_bfloat16* gW[3] = {g_Wh, g_Wm, g_Wl};
#define STAGE_W(c, buf) do {                                                   \
    for (int i = tid; i < 3072; i += 512) {                                    \
        int comp = i >> 10, rem = i & 1023, k = rem >> 3, ch = rem & 7;        \
        uint32_t dst = sb + OFF_W + (buf)*WBUF + comp*WCOMP + k*WPB + ch*16;   \
        cp_async16(dst, gW[comp] + (size_t)k*HH + (c)*64 + ch*8);              \
    }                                                                          \
    CP_COMMIT();                                                               \
} while (0)

    STAGE_W(0, 0);
    __syncthreads();   // X visible to all warps

    int tw = w & 7, nh = w >> 3;
    int tb = tw * 16;
    int g  = lane >> 2, tig = lane & 3;

    // A ldmatrix address (per component): rows tb + (lane&15), col half (lane>>4)
    uint32_t a_addr[3];
#pragma unroll
    for (int comp = 0; comp < 3; ++comp)
        a_addr[comp] = sb + OFF_X + comp*XCOMP + (tb + (lane & 15))*XPB
                     + (lane >> 4)*16;

    float sum_r = 0.f, sum_r8 = 0.f;

    for (int c = 0; c < 8; ++c) {
        int buf = c & 1;
        if (c < 7) STAGE_W(c + 1, buf ^ 1);
        if (c < 7) CP_WAIT(1); else CP_WAIT(0);
        __syncthreads();

        float acc[4][4];
#pragma unroll
        for (int nt = 0; nt < 4; ++nt)
#pragma unroll
            for (int q = 0; q < 4; ++q) acc[nt][q] = 0.f;

#pragma unroll
        for (int ks = 0; ks < 8; ++ks) {
            uint32_t A[3][4];
#pragma unroll
            for (int comp = 0; comp < 3; ++comp)
                ldmatrix_x4(A[comp], a_addr[comp] + ks*32);

            // B rows: k = ks*16 + (lane&15); n byte offset = nh*64 + nt*16
            uint32_t wb = sb + OFF_W + buf*WBUF
                        + (ks*16 + (lane & 15))*WPB + nh*64;
#pragma unroll
            for (int bc = 0; bc < 3; ++bc) {
                uint32_t base = wb + bc*WCOMP;
#pragma unroll
                for (int nt = 0; nt < 4; ++nt) {
                    uint32_t b0, b1r;
                    ldmatrix_x2_t(b0, b1r, base + nt*16);
                    mma16816(acc[nt], A[0], b0, b1r);
                    if (bc < 2)  mma16816(acc[nt], A[1], b0, b1r);
                    if (bc == 0) mma16816(acc[nt], A[2], b0, b1r);
                }
            }
        }

        // epilogue for this chunk: gelu + dot(W2)
#pragma unroll
        for (int nt = 0; nt < 4; ++nt) {
            int cg = c*64 + nh*32 + nt*8 + tig*2;
            float ba = s_b1[cg], bb = s_b1[cg+1];
            float wa = s_w2[cg], wbv = s_w2[cg+1];
            sum_r  += gelu_exact(acc[nt][0] + ba)*wa + gelu_exact(acc[nt][1] + bb)*wbv;
            sum_r8 += gelu_exact(acc[nt][2] + ba)*wa + gelu_exact(acc[nt][3] + bb)*wbv;
        }
        __syncthreads();   // done reading buf before it is overwritten
    }

    // quad reduction (lanes with same row)
    sum_r  += __shfl_xor_sync(0xffffffffu, sum_r, 1);
    sum_r  += __shfl_xor_sync(0xffffffffu, sum_r, 2);
    sum_r8 += __shfl_xor_sync(0xffffffffu, sum_r8, 1);
    sum_r8 += __shfl_xor_sync(0xffffffffu, sum_r8, 2);
    if (tig == 0) {
        s_prt[nh*128 + tb + g]     = sum_r;
        s_prt[nh*128 + tb + g + 8] = sum_r8;
    }
    __syncthreads();
    if (tid < 128)
        g_scores[g0 + tid] = s_prt[tid] + s_prt[128 + tid] + b2v[0];
}

// ---------------- Kernel 5: normalize + top-k + compact ----------------
__device__ __forceinline__ unsigned long long mk_key(float f, int i) {
    unsigned u = __float_as_uint(f);
    u = (u & 0x80000000u) ? ~u : (u | 0x80000000u);  // order-preserving
    return (((unsigned long long)(~u)) << 32) | (unsigned)i; // desc score, asc idx
}

#define TOPK_SMEM (16384 + 32768 + 16384 + 512)
__global__ void __launch_bounds__(1024) topk_kernel(
    float* __restrict__ out_idx, float* __restrict__ out_scores)
{
    extern __shared__ unsigned char shraw[];
    float*              sc   = (float*)shraw;                         // [4096]
    unsigned long long* key  = (unsigned long long*)(shraw + 16384);  // [4096]
    int*                flag = (int*)(shraw + 16384 + 32768);         // [4096]
    float*              redf = (float*)(shraw + 16384 + 32768 + 16384); // 64 f
    int*                redi = (int*)(redf + 64);                     // 64 i

    int b = blockIdx.x, tid = threadIdx.x;
    int lane = tid & 31, wid = tid >> 5;
    int base4 = tid * 4;

    float4 v = *(const float4*)(g_scores + b*TT + base4);
    float s = v.x + v.y + v.z + v.w;
#pragma unroll
    for (int o = 16; o; o >>= 1) s += __shfl_down_sync(0xffffffffu, s, o);
    if (lane == 0) redf[wid] = s;
    __syncthreads();
    if (tid == 0) {
        float a = 0.f;
        for (int i = 0; i < 32; ++i) a += redf[i];
        redf[32] = a * (1.0f/TT);
    }
    __syncthreads();
    float mean = redf[32];
    float d0 = v.x-mean, d1 = v.y-mean, d2 = v.z-mean, d3 = v.w-mean;
    float q = d0*d0 + d1*d1 + d2*d2 + d3*d3;
    __syncthreads();
#pragma unroll
    for (int o = 16; o; o >>= 1) q += __shfl_down_sync(0xffffffffu, q, o);
    if (lane == 0) redf[wid] = q;
    __syncthreads();
    if (tid == 0) {
        float a = 0.f;
        for (int i = 0; i < 32; ++i) a += redf[i];
        redf[33] = 1.0f / (sqrtf(a * (1.0f/TT)) + 1e-6f);
    }
    __syncthreads();
    float inv = redf[33];
    float n0 = d0*inv, n1 = d1*inv, n2 = d2*inv, n3 = d3*inv;

    sc[base4+0] = n0; sc[base4+1] = n1; sc[base4+2] = n2; sc[base4+3] = n3;
    *(float4*)(out_scores + b*TT + base4) = make_float4(n0, n1, n2, n3);
    key[base4+0] = mk_key(n0, base4+0);
    key[base4+1] = mk_key(n1, base4+1);
    key[base4+2] = mk_key(n2, base4+2);
    key[base4+3] = mk_key(n3, base4+3);
    flag[base4+0] = 0; flag[base4+1] = 0; flag[base4+2] = 0; flag[base4+3] = 0;
    __syncthreads();

    // bitonic sort 4096 keys ascending
    for (int kk = 2; kk <= 4096; kk <<= 1) {
        for (int j = kk >> 1; j > 0; j >>= 1) {
#pragma unroll
            for (int p = 0; p < 4; ++p) {
                int i = tid + p*1024;
                int ixj = i ^ j;
                if (ixj > i) {
                    unsigned long long a = key[i], c2 = key[ixj];
                    bool asc = ((i & kk) == 0);
                    if ((a > c2) == asc) { key[i] = c2; key[ixj] = a; }
                }
            }
            __syncthreads();
        }
    }

    // mark top K (positions 0..2047)
    {
        int idx = (int)(unsigned)(key[tid] & 0xffffffffull);
        flag[idx] = 1;
        idx = (int)(unsigned)(key[tid + 1024] & 0xffffffffull);
        flag[idx] = 1;
    }
    __syncthreads();

    // prefix scan of flags, compact ascending
    int f0 = flag[base4], f1 = flag[base4+1], f2 = flag[base4+2], f3 = flag[base4+3];
    int tot = f0 + f1 + f2 + f3;
    int x = tot;
#pragma unroll
    for (int o = 1; o < 32; o <<= 1) {
        int y = __shfl_up_sync(0xffffffffu, x, o);
        if (lane >= o) x += y;
    }
    if (lane == 31) redi[wid] = x;
    __syncthreads();
    if (wid == 0) {
        int y = redi[lane];
        int z = y;
#pragma unroll
        for (int o = 1; o < 32; o <<= 1) {
            int w2 = __shfl_up_sync(0xffffffffu, z, o);
            if (lane >= o) z += w2;
        }
        redi[32 + lane] = z - y;   // exclusive
    }
    __syncthreads();
    int off = redi[32 + wid] + (x - tot);

    int flags[4] = {f0, f1, f2, f3};
#pragma unroll
    for (int qq = 0; qq < 4; ++qq) {
        if (flags[qq]) {
            int idx = base4 + qq;
            int pos = b*KK + off;
            g_selidx[pos] = idx;
            out_idx[pos]  = (float)idx;
            g_gate[pos]   = 1.0f + 0.1f * (1.0f / (1.0f + expf(-sc[idx])));
            ++off;
        }
    }
}

// ---------------- Kernel 6: gather + gate ----------------
__global__ void __launch_bounds__(256) gather_kernel(
    const float* __restrict__ tokens, float* __restrict__ out_sel)
{
    int bk  = blockIdx.x;          // b*K + kk
    int b   = bk >> 11;
    int idx = g_selidx[bk];
    float gate = g_gate[bk];
    const float4* src = (const float4*)(tokens + ((size_t)(b*TT + idx)) * (JJ*CC));
    float4* dst = (float4*)(out_sel + (size_t)bk * (JJ*CC));
#pragma unroll 2
    for (int i = threadIdx.x; i < (JJ*CC)/4; i += 256) {
        float4 v = src[i];
        v.x *= gate; v.y *= gate; v.z *= gate; v.w *= gate;
        dst[i] = v;
    }
}

// ---------------- launch ----------------
extern "C" void kernel_launch(void* const* d_in, const int* in_sizes, int n_in,
                              void* d_out, int out_size)
{
    const float* tokens = (const float*)d_in[0];
    const float* ln_w   = (const float*)d_in[1];
    const float* ln_b   = (const float*)d_in[2];
    const float* W1     = (const float*)d_in[3];
    const float* b1     = (const float*)d_in[4];
    const float* W2     = (const float*)d_in[5];
    const float* b2     = (const float*)d_in[6];

    float* out        = (float*)d_out;
    float* out_sel    = out;                       // [B,K,J,C]
    float* out_idx    = out + SEL_ELEMS;           // [B,K]
    float* out_scores = out_idx + IDX_ELEMS;       // [B,T]

    cudaFuncSetAttribute(mlp_kernel,
        cudaFuncAttributeMaxDynamicSharedMemorySize, MLP_SMEM);
    cudaFuncSetAttribute(topk_kernel,
        cudaFuncAttributeMaxDynamicSharedMemorySize, TOPK_SMEM);

    split_w_kernel<<<256, 256>>>(W1);
    mean_ln_kernel<<<BT, 128>>>(tokens, ln_w, ln_b);
    gc_partial_kernel<<<dim3(BB, 32), 128>>>();
    gc_final_kernel<<<BB, 128>>>();
    mlp_kernel<<<BT/128, 512, MLP_SMEM>>>(b1, W2, b2);
    topk_kernel<<<BB, 1024, TOPK_SMEM>>>(out_idx, out_scores);
    gather_kernel<<<BB*KK, 256>>>(tokens, out_sel);
}